// round 1
// baseline (speedup 1.0000x reference)
#include <cuda_runtime.h>
#include <cuda_bf16.h>
#include <math_constants.h>

// Problem constants (fixed shapes per reference)
#define B_  4
#define S_  2048
#define D_  512
#define H_  8
#define HD_ 64
#define M_  (B_ * S_)      // 8192 rows for projections

// ---------------------------------------------------------------------------
// Scratch (device globals; allocation-free)
// ---------------------------------------------------------------------------
__device__ float g_Q[B_ * H_ * S_ * HD_];   // [B,H,S,hd]
__device__ float g_K[B_ * H_ * S_ * HD_];
__device__ float g_V[B_ * H_ * S_ * HD_];
__device__ float g_A[B_ * S_ * D_];         // merged-head attention output [B,S,D]

// ---------------------------------------------------------------------------
// GEMM: C[M,N] = A[M,K] @ W[K,N] + bias[N]
// headsplit=1 => write C into [B,H,S,hd] layout (m=b*S+s, n=h*64+d)
// BM=128 BN=128 BK=16, 256 threads, 8x8 per thread.
// ---------------------------------------------------------------------------
#define BM 128
#define BN 128
#define BK 16
#define TM 8
#define TN 8

__global__ __launch_bounds__(256, 2)
void gemm_kernel(const float* __restrict__ A, const float* __restrict__ W,
                 const float* __restrict__ bias, float* __restrict__ C,
                 int M, int N, int K, int headsplit)
{
    __shared__ float As[BK][BM];
    __shared__ float Bs[BK][BN];

    const int tid = threadIdx.x;
    const int bx = blockIdx.x;      // N tile
    const int by = blockIdx.y;      // M tile
    const int row0 = by * BM;
    const int col0 = bx * BN;

    const int ty = tid >> 4;        // 0..15
    const int tx = tid & 15;        // 0..15

    float acc[TM][TN];
#pragma unroll
    for (int i = 0; i < TM; i++)
#pragma unroll
        for (int j = 0; j < TN; j++) acc[i][j] = 0.f;

    for (int k0 = 0; k0 < K; k0 += BK) {
        // Load A tile (BM x BK) -> As transposed [BK][BM]
#pragma unroll
        for (int l = 0; l < 2; l++) {
            int f  = tid + l * 256;          // 0..511 float4 slots
            int r  = f >> 2;                 // row in tile 0..127
            int c4 = (f & 3) << 2;           // col 0,4,8,12
            float4 v = *(const float4*)(A + (size_t)(row0 + r) * K + k0 + c4);
            As[c4 + 0][r] = v.x;
            As[c4 + 1][r] = v.y;
            As[c4 + 2][r] = v.z;
            As[c4 + 3][r] = v.w;
        }
        // Load B tile (BK x BN)
#pragma unroll
        for (int l = 0; l < 2; l++) {
            int f  = tid + l * 256;
            int kk = f >> 5;                 // 0..15
            int c4 = (f & 31) << 2;          // 0..124
            *(float4*)(&Bs[kk][c4]) =
                *(const float4*)(W + (size_t)(k0 + kk) * N + col0 + c4);
        }
        __syncthreads();

#pragma unroll
        for (int kk = 0; kk < BK; kk++) {
            float a[TM], b[TN];
#pragma unroll
            for (int i = 0; i < TM; i++) a[i] = As[kk][ty * TM + i];
#pragma unroll
            for (int j = 0; j < TN; j++) b[j] = Bs[kk][tx * TN + j];
#pragma unroll
            for (int i = 0; i < TM; i++)
#pragma unroll
                for (int j = 0; j < TN; j++)
                    acc[i][j] += a[i] * b[j];
        }
        __syncthreads();
    }

    // Epilogue
#pragma unroll
    for (int i = 0; i < TM; i++) {
        int m = row0 + ty * TM + i;
#pragma unroll
        for (int j = 0; j < TN; j++) {
            int n = col0 + tx * TN + j;
            float v = acc[i][j] + bias[n];
            if (headsplit) {
                int b = m >> 11, s = m & (S_ - 1);
                int h = n >> 6,  d = n & (HD_ - 1);
                C[((((size_t)b * H_ + h) * S_) + s) * HD_ + d] = v;
            } else {
                C[(size_t)m * N + n] = v;
            }
        }
    }
}

// ---------------------------------------------------------------------------
// Flash attention (causal), fp32.
// grid: (S/64, B*H), block: 256 threads.
// Per block: 64 q-rows; loop over k-tiles 0..qt (causal skip).
// Thread map: 2 rows x 8 cols per thread.
// Output written merged-head: g_A[b][s][h*64+c].
// ---------------------------------------------------------------------------
#define TQ 64
#define TK 64
#define QS_STRIDE 65   // scalar access, pad to kill stride-64 conflicts
#define KT_STRIDE 68   // float4-aligned padded stride (d-major K^T)
#define VS_STRIDE 68   // float4-aligned padded stride
#define PS_STRIDE 65

// floats: Qs 64*65 + KsT 64*68 + Vs 64*68 + Ps 64*65 + red 64*8
#define ATTN_SMEM_FLOATS (TQ*QS_STRIDE + HD_*KT_STRIDE + TK*VS_STRIDE + TQ*PS_STRIDE + TQ*8)
#define ATTN_SMEM_BYTES  (ATTN_SMEM_FLOATS * 4)

__global__ __launch_bounds__(256, 2)
void attn_kernel(const float* __restrict__ Q, const float* __restrict__ K,
                 const float* __restrict__ V, float* __restrict__ O)
{
    extern __shared__ float sm[];
    float* Qs  = sm;                          // [64][65]  row-major (r,d)
    float* KsT = Qs  + TQ * QS_STRIDE;        // [64][68]  (d, k)  transposed
    float* Vs  = KsT + HD_ * KT_STRIDE;       // [64][68]  (k, c)
    float* Ps  = Vs  + TK * VS_STRIDE;        // [64][65]  (r, k)
    float* red = Ps  + TQ * PS_STRIDE;        // [64][8]

    const int tid  = threadIdx.x;
    const int pair = blockIdx.y;              // b*H + h
    const int qt   = blockIdx.x;
    const int q0   = qt * TQ;

    const float* Qb = Q + (size_t)pair * S_ * HD_;
    const float* Kb = K + (size_t)pair * S_ * HD_;
    const float* Vb = V + (size_t)pair * S_ * HD_;
    const int b = pair >> 3;
    const int h = pair & 7;

    const int rg = tid >> 3;                  // 0..31
    const int cg = tid & 7;                   // 0..7
    const int r0 = rg * 2;                    // thread rows r0, r0+1
    const int c0 = cg * 8;                    // thread cols c0..c0+7

    // --- load Q tile (scaled by 1/sqrt(hd) = 0.125) ---
#pragma unroll
    for (int l = 0; l < 4; l++) {
        int f   = tid + l * 256;              // 0..1023 float4 slots
        int row = f >> 4;                     // 16 float4 per 64-float row
        int c4  = (f & 15) << 2;
        float4 v = *(const float4*)(Qb + (size_t)(q0 + row) * HD_ + c4);
        Qs[row * QS_STRIDE + c4 + 0] = v.x * 0.125f;
        Qs[row * QS_STRIDE + c4 + 1] = v.y * 0.125f;
        Qs[row * QS_STRIDE + c4 + 2] = v.z * 0.125f;
        Qs[row * QS_STRIDE + c4 + 3] = v.w * 0.125f;
    }

    float o[2][8];
#pragma unroll
    for (int i = 0; i < 2; i++)
#pragma unroll
        for (int j = 0; j < 8; j++) o[i][j] = 0.f;
    float m_r[2] = { -CUDART_INF_F, -CUDART_INF_F };
    float l_r[2] = { 0.f, 0.f };

    for (int kt = 0; kt <= qt; kt++) {
        const int k0 = kt * TK;
        __syncthreads();  // prior PV reads of Ks/Vs done

        // --- load K tile transposed -> KsT[d][k], V tile -> Vs[k][c] ---
#pragma unroll
        for (int l = 0; l < 4; l++) {
            int f   = tid + l * 256;
            int row = f >> 4;                 // kv row in tile
            int c4  = (f & 15) << 2;          // head-dim base
            float4 kv = *(const float4*)(Kb + (size_t)(k0 + row) * HD_ + c4);
            KsT[(c4 + 0) * KT_STRIDE + row] = kv.x;
            KsT[(c4 + 1) * KT_STRIDE + row] = kv.y;
            KsT[(c4 + 2) * KT_STRIDE + row] = kv.z;
            KsT[(c4 + 3) * KT_STRIDE + row] = kv.w;
            float4 vv = *(const float4*)(Vb + (size_t)(k0 + row) * HD_ + c4);
            *(float4*)(&Vs[row * VS_STRIDE + c4]) = vv;
        }
        __syncthreads();

        // --- scores: s[i][j] = sum_d Qs[r0+i][d] * K[c0+j][d] ---
        float s[2][8];
#pragma unroll
        for (int i = 0; i < 2; i++)
#pragma unroll
            for (int j = 0; j < 8; j++) s[i][j] = 0.f;

#pragma unroll 8
        for (int d = 0; d < HD_; d++) {
            float q0v = Qs[(r0 + 0) * QS_STRIDE + d];
            float q1v = Qs[(r0 + 1) * QS_STRIDE + d];
            float4 ka = *(const float4*)(&KsT[d * KT_STRIDE + c0]);
            float4 kb = *(const float4*)(&KsT[d * KT_STRIDE + c0 + 4]);
            s[0][0] += q0v * ka.x;  s[0][1] += q0v * ka.y;
            s[0][2] += q0v * ka.z;  s[0][3] += q0v * ka.w;
            s[0][4] += q0v * kb.x;  s[0][5] += q0v * kb.y;
            s[0][6] += q0v * kb.z;  s[0][7] += q0v * kb.w;
            s[1][0] += q1v * ka.x;  s[1][1] += q1v * ka.y;
            s[1][2] += q1v * ka.z;  s[1][3] += q1v * ka.w;
            s[1][4] += q1v * kb.x;  s[1][5] += q1v * kb.y;
            s[1][6] += q1v * kb.z;  s[1][7] += q1v * kb.w;
        }

        // causal mask (only the diagonal tile needs it)
        if (kt == qt) {
#pragma unroll
            for (int i = 0; i < 2; i++) {
                int qg = q0 + r0 + i;
#pragma unroll
                for (int j = 0; j < 8; j++) {
                    int kg = k0 + c0 + j;
                    if (kg > qg) s[i][j] = -CUDART_INF_F;
                }
            }
        }

        // --- row max (8 threads per row) ---
        float lmax[2];
#pragma unroll
        for (int i = 0; i < 2; i++) {
            float mx = s[i][0];
#pragma unroll
            for (int j = 1; j < 8; j++) mx = fmaxf(mx, s[i][j]);
            lmax[i] = mx;
            red[(r0 + i) * 8 + cg] = mx;
        }
        __syncthreads();

        float m_new[2], factor[2];
#pragma unroll
        for (int i = 0; i < 2; i++) {
            float mx = m_r[i];
#pragma unroll
            for (int t = 0; t < 8; t++) mx = fmaxf(mx, red[(r0 + i) * 8 + t]);
            m_new[i]  = mx;
            factor[i] = __expf(m_r[i] - mx);   // exp(-inf)=0 first time
            m_r[i]    = mx;
        }
        __syncthreads();  // red re-use

        // --- p = exp(s - m_new), local sums, write P tile ---
        float lsum[2] = { 0.f, 0.f };
        float p[2][8];
#pragma unroll
        for (int i = 0; i < 2; i++) {
#pragma unroll
            for (int j = 0; j < 8; j++) {
                float pv = __expf(s[i][j] - m_new[i]);
                p[i][j] = pv;
                lsum[i] += pv;
            }
            red[(r0 + i) * 8 + cg] = lsum[i];
#pragma unroll
            for (int j = 0; j < 8; j++)
                Ps[(r0 + i) * PS_STRIDE + c0 + j] = p[i][j];
        }
        __syncthreads();

#pragma unroll
        for (int i = 0; i < 2; i++) {
            float su = 0.f;
#pragma unroll
            for (int t = 0; t < 8; t++) su += red[(r0 + i) * 8 + t];
            l_r[i] = l_r[i] * factor[i] + su;
            // rescale running O
#pragma unroll
            for (int j = 0; j < 8; j++) o[i][j] *= factor[i];
        }

        // --- O += P @ V ---
#pragma unroll 4
        for (int k = 0; k < TK; k++) {
            float p0 = Ps[(r0 + 0) * PS_STRIDE + k];
            float p1 = Ps[(r0 + 1) * PS_STRIDE + k];
            float4 va = *(const float4*)(&Vs[k * VS_STRIDE + c0]);
            float4 vb = *(const float4*)(&Vs[k * VS_STRIDE + c0 + 4]);
            o[0][0] += p0 * va.x;  o[0][1] += p0 * va.y;
            o[0][2] += p0 * va.z;  o[0][3] += p0 * va.w;
            o[0][4] += p0 * vb.x;  o[0][5] += p0 * vb.y;
            o[0][6] += p0 * vb.z;  o[0][7] += p0 * vb.w;
            o[1][0] += p1 * va.x;  o[1][1] += p1 * va.y;
            o[1][2] += p1 * va.z;  o[1][3] += p1 * va.w;
            o[1][4] += p1 * vb.x;  o[1][5] += p1 * vb.y;
            o[1][6] += p1 * vb.z;  o[1][7] += p1 * vb.w;
        }
    }

    // --- normalize + write merged-head output: g_A[b][s][h*64+c] ---
#pragma unroll
    for (int i = 0; i < 2; i++) {
        int qg = q0 + r0 + i;
        float inv = 1.0f / l_r[i];
        float* dst = O + ((size_t)b * S_ + qg) * D_ + h * HD_ + c0;
#pragma unroll
        for (int j = 0; j < 8; j++) dst[j] = o[i][j] * inv;
    }
}

// ---------------------------------------------------------------------------
// Launch
// ---------------------------------------------------------------------------
extern "C" void kernel_launch(void* const* d_in, const int* in_sizes, int n_in,
                              void* d_out, int out_size)
{
    const float* q_in = (const float*)d_in[0];
    const float* k_in = (const float*)d_in[1];
    const float* v_in = (const float*)d_in[2];
    const float* Wq   = (const float*)d_in[3];
    const float* bq   = (const float*)d_in[4];
    const float* Wk   = (const float*)d_in[5];
    const float* bk   = (const float*)d_in[6];
    const float* Wv   = (const float*)d_in[7];
    const float* bv   = (const float*)d_in[8];
    const float* Wo   = (const float*)d_in[9];
    const float* bo   = (const float*)d_in[10];
    float* out = (float*)d_out;

    float *dQ, *dK, *dV, *dA;
    cudaGetSymbolAddress((void**)&dQ, g_Q);
    cudaGetSymbolAddress((void**)&dK, g_K);
    cudaGetSymbolAddress((void**)&dV, g_V);
    cudaGetSymbolAddress((void**)&dA, g_A);

    cudaFuncSetAttribute(attn_kernel,
                         cudaFuncAttributeMaxDynamicSharedMemorySize,
                         ATTN_SMEM_BYTES);

    dim3 gblk(256);
    dim3 ggrid(D_ / BN, M_ / BM);   // (4, 64)

    // QKV projections (head-split epilogue)
    gemm_kernel<<<ggrid, gblk>>>(q_in, Wq, bq, dQ, M_, D_, D_, 1);
    gemm_kernel<<<ggrid, gblk>>>(k_in, Wk, bk, dK, M_, D_, D_, 1);
    gemm_kernel<<<ggrid, gblk>>>(v_in, Wv, bv, dV, M_, D_, D_, 1);

    // causal flash attention -> merged heads in g_A
    dim3 agrid(S_ / TQ, B_ * H_);   // (32, 32)
    attn_kernel<<<agrid, gblk, ATTN_SMEM_BYTES>>>(dQ, dK, dV, dA);

    // output projection
    gemm_kernel<<<ggrid, gblk>>>(dA, Wo, bo, out, M_, D_, D_, 0);
}

// round 3
// speedup vs baseline: 3.6544x; 3.6544x over previous
#include <cuda_runtime.h>
#include <cuda_bf16.h>
#include <math_constants.h>
#include <cstdint>

// Problem constants (fixed shapes per reference)
#define B_  4
#define S_  2048
#define D_  512
#define H_  8
#define HD_ 64
#define M_  (B_ * S_)

typedef __nv_bfloat16 bf16;

// ===========================================================================
// Scratch (device globals; allocation-free)
// ===========================================================================
__device__ bf16 g_Ah[M_ * D_];          // split activations [M,K] row-major
__device__ bf16 g_Al[M_ * D_];
__device__ bf16 g_Bh[D_ * D_];          // split weights, TRANSPOSED [N,K]
__device__ bf16 g_Bl[D_ * D_];
__device__ bf16 g_Qh[B_ * H_ * S_ * HD_];   // [B,H,S,64] (pre-scaled by 0.125)
__device__ bf16 g_Ql[B_ * H_ * S_ * HD_];
__device__ bf16 g_Kh[B_ * H_ * S_ * HD_];
__device__ bf16 g_Kl[B_ * H_ * S_ * HD_];
__device__ bf16 g_Vh[B_ * H_ * S_ * HD_];
__device__ bf16 g_Vl[B_ * H_ * S_ * HD_];

// ===========================================================================
// Helpers
// ===========================================================================
__device__ __forceinline__ void mma16816(float* c, const uint32_t* a, const uint32_t* b)
{
    asm volatile(
        "mma.sync.aligned.m16n8k16.row.col.f32.bf16.bf16.f32 "
        "{%0,%1,%2,%3}, {%4,%5,%6,%7}, {%8,%9}, {%0,%1,%2,%3};"
        : "+f"(c[0]), "+f"(c[1]), "+f"(c[2]), "+f"(c[3])
        : "r"(a[0]), "r"(a[1]), "r"(a[2]), "r"(a[3]), "r"(b[0]), "r"(b[1]));
}

__device__ __forceinline__ void split2(float x, float y, uint32_t& hi, uint32_t& lo)
{
    __nv_bfloat162 h = __floats2bfloat162_rn(x, y);
    float2 hf = __bfloat1622float2(h);
    __nv_bfloat162 l = __floats2bfloat162_rn(x - hf.x, y - hf.y);
    hi = *reinterpret_cast<uint32_t*>(&h);
    lo = *reinterpret_cast<uint32_t*>(&l);
}

// ===========================================================================
// Split kernels: fp32 -> bf16 hi/lo
// ===========================================================================
__global__ __launch_bounds__(256)
void split_in_kernel(const float4* __restrict__ x,
                     uint32_t* __restrict__ hi, uint32_t* __restrict__ lo)
{
    int i = blockIdx.x * 256 + threadIdx.x;      // 0 .. M_*D_/4-1
    float4 v = x[i];
    uint32_t h0, l0, h1, l1;
    split2(v.x, v.y, h0, l0);
    split2(v.z, v.w, h1, l1);
    hi[2 * i + 0] = h0;  hi[2 * i + 1] = h1;
    lo[2 * i + 0] = l0;  lo[2 * i + 1] = l1;
}

// W[K,N] -> Bh/Bl[N,K] (transposed split)
__global__ __launch_bounds__(1024)
void split_wT_kernel(const float* __restrict__ W,
                     bf16* __restrict__ Bh, bf16* __restrict__ Bl)
{
    __shared__ float t[32][33];
    int tx = threadIdx.x, ty = threadIdx.y;
    int k = blockIdx.y * 32 + ty;
    int n = blockIdx.x * 32 + tx;
    t[ty][tx] = W[k * D_ + n];
    __syncthreads();
    int nn = blockIdx.x * 32 + ty;
    int kk = blockIdx.y * 32 + tx;
    float xv = t[tx][ty];
    bf16 h = __float2bfloat16(xv);
    Bh[nn * D_ + kk] = h;
    Bl[nn * D_ + kk] = __float2bfloat16(xv - __bfloat162float(h));
}

// ===========================================================================
// mma.sync bf16-split GEMM: C[M,N] = (Ah+Al)[M,K] @ (Bh+Bl)^T[N,K] + bias
// Block 128x128, 8 warps (4m x 2n -> warp tile 32x64), k-chunk 32.
// mode 0: fp32 out [M,512];  mode 1: bf16 hi/lo split out [B,H,S,64], *scale
// ===========================================================================
#define GSTR 40   // smem row stride in bf16 elems (32 + 8 pad)

__global__ __launch_bounds__(256, 2)
void gemm_mma_kernel(const bf16* __restrict__ Ah, const bf16* __restrict__ Al,
                     const bf16* __restrict__ Bh, const bf16* __restrict__ Bl,
                     const float* __restrict__ bias,
                     float* __restrict__ Cf,
                     bf16* __restrict__ Oh, bf16* __restrict__ Ol,
                     int mode, float scale)
{
    __shared__ bf16 sAh[128 * GSTR];
    __shared__ bf16 sAl[128 * GSTR];
    __shared__ bf16 sBh[128 * GSTR];
    __shared__ bf16 sBl[128 * GSTR];

    const int tid = threadIdx.x;
    const int wid = tid >> 5;
    const int lane = tid & 31;
    const int gid = lane >> 2;
    const int tig = lane & 3;
    const int wm = wid >> 1;          // 0..3
    const int wn = wid & 1;           // 0..1
    const int row0 = blockIdx.y * 128;
    const int col0 = blockIdx.x * 128;

    float c[2][8][4];
#pragma unroll
    for (int mt = 0; mt < 2; mt++)
#pragma unroll
        for (int nt = 0; nt < 8; nt++)
#pragma unroll
            for (int j = 0; j < 4; j++) c[mt][nt][j] = 0.f;

    for (int k0 = 0; k0 < D_; k0 += 32) {
        __syncthreads();
#pragma unroll
        for (int i = 0; i < 2; i++) {
            int idx = tid + i * 256;           // 0..511
            int r = idx >> 2, u = (idx & 3) * 8;
            *(uint4*)&sAh[r * GSTR + u] = *(const uint4*)(Ah + (size_t)(row0 + r) * D_ + k0 + u);
            *(uint4*)&sAl[r * GSTR + u] = *(const uint4*)(Al + (size_t)(row0 + r) * D_ + k0 + u);
            *(uint4*)&sBh[r * GSTR + u] = *(const uint4*)(Bh + (size_t)(col0 + r) * D_ + k0 + u);
            *(uint4*)&sBl[r * GSTR + u] = *(const uint4*)(Bl + (size_t)(col0 + r) * D_ + k0 + u);
        }
        __syncthreads();

#pragma unroll
        for (int ks = 0; ks < 2; ks++) {
            uint32_t ah[2][4], al[2][4];
#pragma unroll
            for (int mt = 0; mt < 2; mt++) {
                int rbase = wm * 32 + mt * 16;
#pragma unroll
                for (int i = 0; i < 4; i++) {
                    int r = rbase + gid + 8 * (i & 1);
                    int cc = ks * 16 + tig * 2 + 8 * (i >> 1);
                    ah[mt][i] = *(const uint32_t*)&sAh[r * GSTR + cc];
                    al[mt][i] = *(const uint32_t*)&sAl[r * GSTR + cc];
                }
            }
#pragma unroll
            for (int nt = 0; nt < 8; nt++) {
                int n = wn * 64 + nt * 8 + gid;
                uint32_t bh[2], bl[2];
                bh[0] = *(const uint32_t*)&sBh[n * GSTR + ks * 16 + tig * 2];
                bh[1] = *(const uint32_t*)&sBh[n * GSTR + ks * 16 + 8 + tig * 2];
                bl[0] = *(const uint32_t*)&sBl[n * GSTR + ks * 16 + tig * 2];
                bl[1] = *(const uint32_t*)&sBl[n * GSTR + ks * 16 + 8 + tig * 2];
#pragma unroll
                for (int mt = 0; mt < 2; mt++) {
                    mma16816(c[mt][nt], ah[mt], bh);
                    mma16816(c[mt][nt], ah[mt], bl);
                    mma16816(c[mt][nt], al[mt], bh);
                }
            }
        }
    }

    // Epilogue
#pragma unroll
    for (int mt = 0; mt < 2; mt++) {
        int m = row0 + wm * 32 + mt * 16 + gid;
#pragma unroll
        for (int nt = 0; nt < 8; nt++) {
            int n = col0 + wn * 64 + nt * 8 + tig * 2;
            float b0 = bias[n], b1 = bias[n + 1];
            float v00 = c[mt][nt][0] + b0, v01 = c[mt][nt][1] + b1;   // row m
            float v10 = c[mt][nt][2] + b0, v11 = c[mt][nt][3] + b1;   // row m+8
            if (mode == 0) {
                *(float2*)(Cf + (size_t)m * D_ + n)       = make_float2(v00, v01);
                *(float2*)(Cf + (size_t)(m + 8) * D_ + n) = make_float2(v10, v11);
            } else {
                v00 *= scale; v01 *= scale; v10 *= scale; v11 *= scale;
                int bb = m >> 11, h = n >> 6, d = n & 63;
                int s0 = m & (S_ - 1);
                size_t off0 = (((size_t)(bb * H_ + h) * S_) + s0) * HD_ + d;
                size_t off1 = off0 + 8 * HD_;
                uint32_t hi, lo;
                split2(v00, v01, hi, lo);
                *(uint32_t*)(Oh + off0) = hi; *(uint32_t*)(Ol + off0) = lo;
                split2(v10, v11, hi, lo);
                *(uint32_t*)(Oh + off1) = hi; *(uint32_t*)(Ol + off1) = lo;
            }
        }
    }
}

// ===========================================================================
// Flash attention with mma.sync, bf16-split, causal.
// grid (S/64, B*H), block 128 (4 warps, 16 q-rows each).
// Writes output as bf16 hi/lo split directly into g_Ah/g_Al [M,512].
// ===========================================================================
#define AQSTR 72   // bf16 elems per row (64 + 8)
#define AVSTR 36   // uint32 per VT row (32 + 4)

#define ATTN_SMEM_BYTES (4 * 64 * AQSTR * 2 + 2 * 64 * AVSTR * 4)   // 55296

__global__ __launch_bounds__(128, 4)
void attn_mma_kernel(const bf16* __restrict__ Qh, const bf16* __restrict__ Ql,
                     const bf16* __restrict__ Kh, const bf16* __restrict__ Kl,
                     const bf16* __restrict__ Vh, const bf16* __restrict__ Vl,
                     bf16* __restrict__ Oh, bf16* __restrict__ Ol)
{
    extern __shared__ char smem[];
    bf16* sQh = (bf16*)smem;
    bf16* sQl = sQh + 64 * AQSTR;
    bf16* sKh = sQl + 64 * AQSTR;
    bf16* sKl = sKh + 64 * AQSTR;
    uint32_t* sVh = (uint32_t*)(sKl + 64 * AQSTR);   // [64 d][36] packed s-pairs
    uint32_t* sVl = sVh + 64 * AVSTR;

    const int tid = threadIdx.x;
    const int wid = tid >> 5;
    const int lane = tid & 31;
    const int gid = lane >> 2;
    const int tig = lane & 3;

    const int qt = blockIdx.x;
    const int pair = blockIdx.y;
    const int q0 = qt * 64;
    const size_t base = (size_t)pair * S_ * HD_;

    // --- stage Q tile (hi/lo) ---
#pragma unroll
    for (int i = 0; i < 4; i++) {
        int idx = tid + i * 128;
        int r = idx >> 3, u = (idx & 7) * 8;
        *(uint4*)&sQh[r * AQSTR + u] = *(const uint4*)(Qh + base + (size_t)(q0 + r) * HD_ + u);
        *(uint4*)&sQl[r * AQSTR + u] = *(const uint4*)(Ql + base + (size_t)(q0 + r) * HD_ + u);
    }
    __syncthreads();

    // Q a-frags in registers, 4 hd k-steps
    uint32_t qh[4][4], ql[4][4];
#pragma unroll
    for (int ks = 0; ks < 4; ks++)
#pragma unroll
        for (int i = 0; i < 4; i++) {
            int r = wid * 16 + gid + 8 * (i & 1);
            int cc = ks * 16 + tig * 2 + 8 * (i >> 1);
            qh[ks][i] = *(const uint32_t*)&sQh[r * AQSTR + cc];
            ql[ks][i] = *(const uint32_t*)&sQl[r * AQSTR + cc];
        }

    float o[8][4];
#pragma unroll
    for (int nt = 0; nt < 8; nt++)
#pragma unroll
        for (int j = 0; j < 4; j++) o[nt][j] = 0.f;
    float m0 = -CUDART_INF_F, m1 = -CUDART_INF_F;
    float l0 = 0.f, l1 = 0.f;

    for (int kt = 0; kt <= qt; kt++) {
        const int k0 = kt * 64;
        __syncthreads();

        // --- load K tiles ---
#pragma unroll
        for (int i = 0; i < 4; i++) {
            int idx = tid + i * 128;
            int r = idx >> 3, u = (idx & 7) * 8;
            *(uint4*)&sKh[r * AQSTR + u] = *(const uint4*)(Kh + base + (size_t)(k0 + r) * HD_ + u);
            *(uint4*)&sKl[r * AQSTR + u] = *(const uint4*)(Kl + base + (size_t)(k0 + r) * HD_ + u);
        }
        // --- load V with transpose + s-pair pack: sV[d][sp] = {V[2sp][d], V[2sp+1][d]} ---
        {
            int d0 = (tid & 7) * 8;
#pragma unroll
            for (int i = 0; i < 2; i++) {
                int sp = (tid >> 3) + i * 16;
                const bf16* va = Vh + base + (size_t)(k0 + 2 * sp) * HD_ + d0;
                uint4 a = *(const uint4*)va;
                uint4 b = *(const uint4*)(va + HD_);
                const unsigned short* au = (const unsigned short*)&a;
                const unsigned short* bu = (const unsigned short*)&b;
#pragma unroll
                for (int j = 0; j < 8; j++)
                    sVh[(d0 + j) * AVSTR + sp] = (uint32_t)au[j] | ((uint32_t)bu[j] << 16);
                const bf16* vc = Vl + base + (size_t)(k0 + 2 * sp) * HD_ + d0;
                uint4 e = *(const uint4*)vc;
                uint4 f = *(const uint4*)(vc + HD_);
                const unsigned short* eu = (const unsigned short*)&e;
                const unsigned short* fu = (const unsigned short*)&f;
#pragma unroll
                for (int j = 0; j < 8; j++)
                    sVl[(d0 + j) * AVSTR + sp] = (uint32_t)eu[j] | ((uint32_t)fu[j] << 16);
            }
        }
        __syncthreads();

        // --- scores ---
        float c[8][4];
#pragma unroll
        for (int nt = 0; nt < 8; nt++)
#pragma unroll
            for (int j = 0; j < 4; j++) c[nt][j] = 0.f;

#pragma unroll
        for (int nt = 0; nt < 8; nt++) {
            int n = nt * 8 + gid;
#pragma unroll
            for (int ks = 0; ks < 4; ks++) {
                uint32_t bh[2], bl[2];
                bh[0] = *(const uint32_t*)&sKh[n * AQSTR + ks * 16 + tig * 2];
                bh[1] = *(const uint32_t*)&sKh[n * AQSTR + ks * 16 + 8 + tig * 2];
                bl[0] = *(const uint32_t*)&sKl[n * AQSTR + ks * 16 + tig * 2];
                bl[1] = *(const uint32_t*)&sKl[n * AQSTR + ks * 16 + 8 + tig * 2];
                mma16816(c[nt], qh[ks], bh);
                mma16816(c[nt], qh[ks], bl);
                mma16816(c[nt], ql[ks], bh);
            }
        }

        // --- causal mask (diagonal tile only) ---
        if (kt == qt) {
            int rg = q0 + wid * 16 + gid;
#pragma unroll
            for (int nt = 0; nt < 8; nt++) {
                int cb = k0 + nt * 8 + tig * 2;
                if (cb     > rg)     c[nt][0] = -CUDART_INF_F;
                if (cb + 1 > rg)     c[nt][1] = -CUDART_INF_F;
                if (cb     > rg + 8) c[nt][2] = -CUDART_INF_F;
                if (cb + 1 > rg + 8) c[nt][3] = -CUDART_INF_F;
            }
        }

        // --- online softmax (rows gid, gid+8 of this warp stripe) ---
        float mx0 = c[0][0], mx1 = c[0][2];
#pragma unroll
        for (int nt = 0; nt < 8; nt++) {
            mx0 = fmaxf(mx0, fmaxf(c[nt][0], c[nt][1]));
            mx1 = fmaxf(mx1, fmaxf(c[nt][2], c[nt][3]));
        }
        mx0 = fmaxf(mx0, __shfl_xor_sync(0xffffffffu, mx0, 1));
        mx0 = fmaxf(mx0, __shfl_xor_sync(0xffffffffu, mx0, 2));
        mx1 = fmaxf(mx1, __shfl_xor_sync(0xffffffffu, mx1, 1));
        mx1 = fmaxf(mx1, __shfl_xor_sync(0xffffffffu, mx1, 2));

        float mn0 = fmaxf(m0, mx0), mn1 = fmaxf(m1, mx1);
        float f0 = __expf(m0 - mn0), f1 = __expf(m1 - mn1);
        m0 = mn0; m1 = mn1;

        float s0 = 0.f, s1 = 0.f;
#pragma unroll
        for (int nt = 0; nt < 8; nt++) {
            c[nt][0] = __expf(c[nt][0] - mn0);
            c[nt][1] = __expf(c[nt][1] - mn0);
            c[nt][2] = __expf(c[nt][2] - mn1);
            c[nt][3] = __expf(c[nt][3] - mn1);
            s0 += c[nt][0] + c[nt][1];
            s1 += c[nt][2] + c[nt][3];
        }
        s0 += __shfl_xor_sync(0xffffffffu, s0, 1);
        s0 += __shfl_xor_sync(0xffffffffu, s0, 2);
        s1 += __shfl_xor_sync(0xffffffffu, s1, 1);
        s1 += __shfl_xor_sync(0xffffffffu, s1, 2);
        l0 = l0 * f0 + s0;
        l1 = l1 * f1 + s1;
#pragma unroll
        for (int nt = 0; nt < 8; nt++) {
            o[nt][0] *= f0; o[nt][1] *= f0;
            o[nt][2] *= f1; o[nt][3] *= f1;
        }

        // --- P @ V (split P from score fragments) ---
#pragma unroll
        for (int ks = 0; ks < 4; ks++) {
            uint32_t pah[4], pal[4];
            split2(c[2 * ks][0],     c[2 * ks][1],     pah[0], pal[0]);
            split2(c[2 * ks][2],     c[2 * ks][3],     pah[1], pal[1]);
            split2(c[2 * ks + 1][0], c[2 * ks + 1][1], pah[2], pal[2]);
            split2(c[2 * ks + 1][2], c[2 * ks + 1][3], pah[3], pal[3]);
#pragma unroll
            for (int nt = 0; nt < 8; nt++) {
                int n = nt * 8 + gid;
                uint32_t bh[2], bl[2];
                bh[0] = sVh[n * AVSTR + ks * 8 + tig];
                bh[1] = sVh[n * AVSTR + ks * 8 + 4 + tig];
                bl[0] = sVl[n * AVSTR + ks * 8 + tig];
                bl[1] = sVl[n * AVSTR + ks * 8 + 4 + tig];
                mma16816(o[nt], pah, bh);
                mma16816(o[nt], pah, bl);
                mma16816(o[nt], pal, bh);
            }
        }
    }

    // --- epilogue: normalize, split to bf16 hi/lo merged-head [M,512] ---
    float inv0 = 1.0f / l0, inv1 = 1.0f / l1;
    const int bb = pair >> 3, h = pair & 7;
    const int rg = q0 + wid * 16 + gid;
    const size_t r0off = ((size_t)bb * S_ + rg) * D_ + h * HD_;
    const size_t r1off = r0off + 8 * D_;
#pragma unroll
    for (int nt = 0; nt < 8; nt++) {
        int d = nt * 8 + tig * 2;
        uint32_t hi, lo;
        split2(o[nt][0] * inv0, o[nt][1] * inv0, hi, lo);
        *(uint32_t*)(Oh + r0off + d) = hi;
        *(uint32_t*)(Ol + r0off + d) = lo;
        split2(o[nt][2] * inv1, o[nt][3] * inv1, hi, lo);
        *(uint32_t*)(Oh + r1off + d) = hi;
        *(uint32_t*)(Ol + r1off + d) = lo;
    }
}

// ===========================================================================
// Launch
// ===========================================================================
extern "C" void kernel_launch(void* const* d_in, const int* in_sizes, int n_in,
                              void* d_out, int out_size)
{
    const float* q_in = (const float*)d_in[0];
    const float* k_in = (const float*)d_in[1];
    const float* v_in = (const float*)d_in[2];
    const float* Wq   = (const float*)d_in[3];
    const float* bq   = (const float*)d_in[4];
    const float* Wk   = (const float*)d_in[5];
    const float* bk   = (const float*)d_in[6];
    const float* Wv   = (const float*)d_in[7];
    const float* bv   = (const float*)d_in[8];
    const float* Wo   = (const float*)d_in[9];
    const float* bo   = (const float*)d_in[10];
    float* out = (float*)d_out;

    bf16 *dAh, *dAl, *dBh, *dBl, *dQh, *dQl, *dKh, *dKl, *dVh, *dVl;
    cudaGetSymbolAddress((void**)&dAh, g_Ah);
    cudaGetSymbolAddress((void**)&dAl, g_Al);
    cudaGetSymbolAddress((void**)&dBh, g_Bh);
    cudaGetSymbolAddress((void**)&dBl, g_Bl);
    cudaGetSymbolAddress((void**)&dQh, g_Qh);
    cudaGetSymbolAddress((void**)&dQl, g_Ql);
    cudaGetSymbolAddress((void**)&dKh, g_Kh);
    cudaGetSymbolAddress((void**)&dKl, g_Kl);
    cudaGetSymbolAddress((void**)&dVh, g_Vh);
    cudaGetSymbolAddress((void**)&dVl, g_Vl);

    cudaFuncSetAttribute(attn_mma_kernel,
                         cudaFuncAttributeMaxDynamicSharedMemorySize,
                         ATTN_SMEM_BYTES);

    dim3 wblk(32, 32);
    dim3 wgrid(D_ / 32, D_ / 32);                 // (16,16)
    dim3 ggrid(D_ / 128, M_ / 128);               // (4, 64)
    const int sgrid = (M_ * D_ / 4) / 256;

    // Q projection (pre-scaled by 1/sqrt(hd) = 0.125)
    split_wT_kernel<<<wgrid, wblk>>>(Wq, dBh, dBl);
    split_in_kernel<<<sgrid, 256>>>((const float4*)q_in, (uint32_t*)dAh, (uint32_t*)dAl);
    gemm_mma_kernel<<<ggrid, 256>>>(dAh, dAl, dBh, dBl, bq, nullptr, dQh, dQl, 1, 0.125f);

    // K projection
    split_wT_kernel<<<wgrid, wblk>>>(Wk, dBh, dBl);
    split_in_kernel<<<sgrid, 256>>>((const float4*)k_in, (uint32_t*)dAh, (uint32_t*)dAl);
    gemm_mma_kernel<<<ggrid, 256>>>(dAh, dAl, dBh, dBl, bk, nullptr, dKh, dKl, 1, 1.0f);

    // V projection
    split_wT_kernel<<<wgrid, wblk>>>(Wv, dBh, dBl);
    split_in_kernel<<<sgrid, 256>>>((const float4*)v_in, (uint32_t*)dAh, (uint32_t*)dAl);
    gemm_mma_kernel<<<ggrid, 256>>>(dAh, dAl, dBh, dBl, bv, nullptr, dVh, dVl, 1, 1.0f);

    // causal flash attention -> split merged-head output into g_Ah/g_Al
    dim3 agrid(S_ / 64, B_ * H_);                 // (32, 32)
    attn_mma_kernel<<<agrid, 128, ATTN_SMEM_BYTES>>>(dQh, dQl, dKh, dKl, dVh, dVl, dAh, dAl);

    // output projection (fp32 out)
    split_wT_kernel<<<wgrid, wblk>>>(Wo, dBh, dBl);
    gemm_mma_kernel<<<ggrid, 256>>>(dAh, dAl, dBh, dBl, bo, out, nullptr, nullptr, 0, 1.0f);
}

// round 6
// speedup vs baseline: 4.2039x; 1.1504x over previous
#include <cuda_runtime.h>
#include <cuda_bf16.h>
#include <math_constants.h>
#include <cstdint>

// Problem constants (fixed shapes per reference)
#define B_  4
#define S_  2048
#define D_  512
#define H_  8
#define HD_ 64
#define M_  (B_ * S_)
#define DD_ (D_ * D_)

typedef __nv_bfloat16 bf16;

// ===========================================================================
// Scratch (device globals; allocation-free)
// ===========================================================================
__device__ bf16 g_Aqh[M_ * D_];         // split activations [M,K] row-major
__device__ bf16 g_Aql[M_ * D_];
__device__ bf16 g_Akh[M_ * D_];
__device__ bf16 g_Akl[M_ * D_];
__device__ bf16 g_Avh[M_ * D_];
__device__ bf16 g_Avl[M_ * D_];
__device__ bf16 g_Bh[4 * DD_];          // split weights, TRANSPOSED [N,K] (x4)
__device__ bf16 g_Bl[4 * DD_];
__device__ bf16 g_Qh[B_ * H_ * S_ * HD_];   // [B,H,S,64] (pre-scaled 0.125)
__device__ bf16 g_Ql[B_ * H_ * S_ * HD_];
__device__ bf16 g_Kh[B_ * H_ * S_ * HD_];
__device__ bf16 g_Kl[B_ * H_ * S_ * HD_];
__device__ bf16 g_Vh[B_ * H_ * S_ * HD_];
__device__ bf16 g_Vl[B_ * H_ * S_ * HD_];
__device__ bf16 g_VTh[B_ * H_ * HD_ * S_];  // [B,H,64,S]
__device__ bf16 g_VTl[B_ * H_ * HD_ * S_];

// ===========================================================================
// Helpers
// ===========================================================================
__device__ __forceinline__ uint32_t smem_u32(const void* p) {
    uint32_t a;
    asm("{ .reg .u64 t; cvta.to.shared.u64 t, %1; cvt.u32.u64 %0, t; }"
        : "=r"(a) : "l"(p));
    return a;
}

__device__ __forceinline__ void cpa16(uint32_t dst, const void* src) {
    asm volatile("cp.async.ca.shared.global [%0], [%1], 16;"
                 :: "r"(dst), "l"(src) : "memory");
}
#define CPA_COMMIT() asm volatile("cp.async.commit_group;" ::: "memory")
#define CPA_WAIT(N)  asm volatile("cp.async.wait_group %0;" :: "n"(N) : "memory")

__device__ __forceinline__ void mma16816(float* c, const uint32_t* a, const uint32_t* b)
{
    asm volatile(
        "mma.sync.aligned.m16n8k16.row.col.f32.bf16.bf16.f32 "
        "{%0,%1,%2,%3}, {%4,%5,%6,%7}, {%8,%9}, {%0,%1,%2,%3};"
        : "+f"(c[0]), "+f"(c[1]), "+f"(c[2]), "+f"(c[3])
        : "r"(a[0]), "r"(a[1]), "r"(a[2]), "r"(a[3]), "r"(b[0]), "r"(b[1]));
}

__device__ __forceinline__ void split2(float x, float y, uint32_t& hi, uint32_t& lo)
{
    __nv_bfloat162 h = __floats2bfloat162_rn(x, y);
    float2 hf = __bfloat1622float2(h);
    __nv_bfloat162 l = __floats2bfloat162_rn(x - hf.x, y - hf.y);
    hi = *reinterpret_cast<uint32_t*>(&h);
    lo = *reinterpret_cast<uint32_t*>(&l);
}

// ===========================================================================
// Fused split kernels
// ===========================================================================
__global__ __launch_bounds__(256)
void split_in3_kernel(const float4* __restrict__ x0, const float4* __restrict__ x1,
                      const float4* __restrict__ x2,
                      uint32_t* __restrict__ h0, uint32_t* __restrict__ l0,
                      uint32_t* __restrict__ h1, uint32_t* __restrict__ l1,
                      uint32_t* __restrict__ h2, uint32_t* __restrict__ l2)
{
    const int y = blockIdx.y;
    const float4* x = (y == 0) ? x0 : (y == 1) ? x1 : x2;
    uint32_t* hi = (y == 0) ? h0 : (y == 1) ? h1 : h2;
    uint32_t* lo = (y == 0) ? l0 : (y == 1) ? l1 : l2;
    int i = blockIdx.x * 256 + threadIdx.x;
    float4 v = x[i];
    uint32_t a0, b0, a1, b1;
    split2(v.x, v.y, a0, b0);
    split2(v.z, v.w, a1, b1);
    hi[2 * i + 0] = a0;  hi[2 * i + 1] = a1;
    lo[2 * i + 0] = b0;  lo[2 * i + 1] = b1;
}

// All 4 weights: W[K,N] -> Bh/Bl[N,K] (transposed split), z selects weight
__global__ __launch_bounds__(1024)
void split_w4_kernel(const float* __restrict__ Wq, const float* __restrict__ Wk,
                     const float* __restrict__ Wv, const float* __restrict__ Wo,
                     bf16* __restrict__ Bh, bf16* __restrict__ Bl)
{
    __shared__ float t[32][33];
    const float* Ws[4] = {Wq, Wk, Wv, Wo};
    const float* W = Ws[blockIdx.z];
    bf16* BhD = Bh + (size_t)blockIdx.z * DD_;
    bf16* BlD = Bl + (size_t)blockIdx.z * DD_;
    int tx = threadIdx.x, ty = threadIdx.y;
    int k = blockIdx.y * 32 + ty;
    int n = blockIdx.x * 32 + tx;
    t[ty][tx] = W[k * D_ + n];
    __syncthreads();
    int nn = blockIdx.x * 32 + ty;
    int kk = blockIdx.y * 32 + tx;
    float xv = t[tx][ty];
    bf16 h = __float2bfloat16(xv);
    BhD[nn * D_ + kk] = h;
    BlD[nn * D_ + kk] = __float2bfloat16(xv - __bfloat162float(h));
}

// ===========================================================================
// V transpose: [B,H,S,64] -> [B,H,64,S] (hi and lo)
// ===========================================================================
__global__ __launch_bounds__(256)
void vt_kernel(const bf16* __restrict__ Vh, const bf16* __restrict__ Vl,
               bf16* __restrict__ VTh, bf16* __restrict__ VTl)
{
    __shared__ uint32_t t[2][32][33];
    const int tx = threadIdx.x & 31;
    const int ty = threadIdx.x >> 5;     // 0..7
    const int pair = blockIdx.z;
    const int s0 = blockIdx.x * 32;
    const int d0 = blockIdx.y * 32;
    const size_t ib = (size_t)pair * S_ * HD_;
    const size_t ob = (size_t)pair * HD_ * S_;
    const unsigned short* vh = (const unsigned short*)Vh;
    const unsigned short* vl = (const unsigned short*)Vl;
#pragma unroll
    for (int i = 0; i < 4; i++) {
        int r = ty + 8 * i;
        t[0][r][tx] = vh[ib + (size_t)(s0 + r) * HD_ + d0 + tx];
        t[1][r][tx] = vl[ib + (size_t)(s0 + r) * HD_ + d0 + tx];
    }
    __syncthreads();
    unsigned short* oh = (unsigned short*)VTh;
    unsigned short* ol = (unsigned short*)VTl;
#pragma unroll
    for (int i = 0; i < 4; i++) {
        int r = ty + 8 * i;  // d within tile
        oh[ob + (size_t)(d0 + r) * S_ + s0 + tx] = (unsigned short)t[0][tx][r];
        ol[ob + (size_t)(d0 + r) * S_ + s0 + tx] = (unsigned short)t[1][tx][r];
    }
}

// ===========================================================================
// mma.sync bf16-split GEMM, cp.async 2-stage pipeline.
// Block 128x128, 8 warps (4m x 2n -> warp tile 32x64), k-chunk 32.
// mode 0: fp32 out [M,512];  mode 1: bf16 hi/lo split out [B,H,S,64], *scale
// ===========================================================================
#define GKC 32
#define GSTR 40                              // smem row stride (elems)
#define G_ARR_B (128 * GSTR * 2)             // 10240 bytes per array
#define G_STAGE_B (4 * G_ARR_B)              // 40960 bytes per stage
#define GEMM_SMEM_BYTES (2 * G_STAGE_B)      // 81920

__global__ __launch_bounds__(256)
void gemm_mma_kernel(const bf16* __restrict__ Ah, const bf16* __restrict__ Al,
                     const bf16* __restrict__ Bh, const bf16* __restrict__ Bl,
                     const float* __restrict__ bias,
                     float* __restrict__ Cf,
                     bf16* __restrict__ Oh, bf16* __restrict__ Ol,
                     int mode, float scale)
{
    extern __shared__ char gsm[];
    const uint32_t sb = smem_u32(gsm);
    const int tid = threadIdx.x;
    const int wid = tid >> 5;
    const int lane = tid & 31;
    const int gid = lane >> 2;
    const int tig = lane & 3;
    const int wm = wid >> 1;
    const int wn = wid & 1;
    const int row0 = blockIdx.y * 128;
    const int col0 = blockIdx.x * 128;

    float c[2][8][4];
#pragma unroll
    for (int mt = 0; mt < 2; mt++)
#pragma unroll
        for (int nt = 0; nt < 8; nt++)
#pragma unroll
            for (int j = 0; j < 4; j++) c[mt][nt][j] = 0.f;

    const int NC = D_ / GKC;   // 16

    // async stage loader: chunk cc -> stage st
    auto issue = [&](int cc, int st) {
        const size_t aoff = (size_t)row0 * D_ + cc * GKC;
        const size_t boff = (size_t)col0 * D_ + cc * GKC;
        const bf16* srcs[4] = { Ah + aoff, Al + aoff, Bh + boff, Bl + boff };
        const uint32_t dst0 = sb + st * G_STAGE_B;
#pragma unroll
        for (int i = 0; i < 8; i++) {
            int idx = tid + i * 256;
            int arr = idx >> 9, rem = idx & 511;
            int r = rem >> 2, u = (rem & 3) << 3;
            cpa16(dst0 + arr * G_ARR_B + (r * GSTR + u) * 2,
                  srcs[arr] + (size_t)r * D_ + u);
        }
        CPA_COMMIT();
    };

    issue(0, 0);
#pragma unroll 1
    for (int cc = 0; cc < NC; cc++) {
        const int st = cc & 1;
        if (cc + 1 < NC) { issue(cc + 1, st ^ 1); CPA_WAIT(1); }
        else             { CPA_WAIT(0); }
        __syncthreads();

        const bf16* sAh = (const bf16*)(gsm + st * G_STAGE_B);
        const bf16* sAl = sAh + 128 * GSTR;
        const bf16* sBh = sAl + 128 * GSTR;
        const bf16* sBl = sBh + 128 * GSTR;

#pragma unroll
        for (int ks = 0; ks < 2; ks++) {
            uint32_t ah[2][4], al[2][4];
#pragma unroll
            for (int mt = 0; mt < 2; mt++) {
                int rbase = wm * 32 + mt * 16;
#pragma unroll
                for (int i = 0; i < 4; i++) {
                    int r = rbase + gid + 8 * (i & 1);
                    int col = ks * 16 + tig * 2 + 8 * (i >> 1);
                    ah[mt][i] = *(const uint32_t*)&sAh[r * GSTR + col];
                    al[mt][i] = *(const uint32_t*)&sAl[r * GSTR + col];
                }
            }
#pragma unroll
            for (int nt = 0; nt < 8; nt++) {
                int n = wn * 64 + nt * 8 + gid;
                uint32_t bh[2], bl[2];
                bh[0] = *(const uint32_t*)&sBh[n * GSTR + ks * 16 + tig * 2];
                bh[1] = *(const uint32_t*)&sBh[n * GSTR + ks * 16 + 8 + tig * 2];
                bl[0] = *(const uint32_t*)&sBl[n * GSTR + ks * 16 + tig * 2];
                bl[1] = *(const uint32_t*)&sBl[n * GSTR + ks * 16 + 8 + tig * 2];
#pragma unroll
                for (int mt = 0; mt < 2; mt++) {
                    mma16816(c[mt][nt], ah[mt], bh);
                    mma16816(c[mt][nt], ah[mt], bl);
                    mma16816(c[mt][nt], al[mt], bh);
                }
            }
        }
        __syncthreads();
    }

    // Epilogue
#pragma unroll
    for (int mt = 0; mt < 2; mt++) {
        int m = row0 + wm * 32 + mt * 16 + gid;
#pragma unroll
        for (int nt = 0; nt < 8; nt++) {
            int n = col0 + wn * 64 + nt * 8 + tig * 2;
            float b0 = bias[n], b1 = bias[n + 1];
            float v00 = c[mt][nt][0] + b0, v01 = c[mt][nt][1] + b1;
            float v10 = c[mt][nt][2] + b0, v11 = c[mt][nt][3] + b1;
            if (mode == 0) {
                *(float2*)(Cf + (size_t)m * D_ + n)       = make_float2(v00, v01);
                *(float2*)(Cf + (size_t)(m + 8) * D_ + n) = make_float2(v10, v11);
            } else {
                v00 *= scale; v01 *= scale; v10 *= scale; v11 *= scale;
                int bb = m >> 11, h = n >> 6, d = n & 63;
                int s0 = m & (S_ - 1);
                size_t off0 = (((size_t)(bb * H_ + h) * S_) + s0) * HD_ + d;
                size_t off1 = off0 + 8 * HD_;
                uint32_t hi, lo;
                split2(v00, v01, hi, lo);
                *(uint32_t*)(Oh + off0) = hi; *(uint32_t*)(Ol + off0) = lo;
                split2(v10, v11, hi, lo);
                *(uint32_t*)(Oh + off1) = hi; *(uint32_t*)(Ol + off1) = lo;
            }
        }
    }
}

// ===========================================================================
// Flash attention with mma.sync, bf16-split, causal. V pre-transposed.
// grid (S/64, B*H), block 128 (4 warps, 16 q-rows each).
// qt remapped descending for wave load balance.
// ===========================================================================
#define AQSTR 72                       // bf16 elems per smem row
#define A_ARR_B (64 * AQSTR * 2)       // 9216 bytes
#define ATTN_SMEM_BYTES (6 * A_ARR_B)  // 55296

__global__ __launch_bounds__(128, 4)
void attn_mma_kernel(const bf16* __restrict__ Qh, const bf16* __restrict__ Ql,
                     const bf16* __restrict__ Kh, const bf16* __restrict__ Kl,
                     const bf16* __restrict__ VTh, const bf16* __restrict__ VTl,
                     bf16* __restrict__ Oh, bf16* __restrict__ Ol)
{
    extern __shared__ char smemc[];
    const uint32_t sb = smem_u32(smemc);
    bf16* sQh = (bf16*)smemc;
    bf16* sQl = sQh + 64 * AQSTR;
    bf16* sKh = sQl + 64 * AQSTR;
    bf16* sKl = sKh + 64 * AQSTR;
    bf16* sVh = sKl + 64 * AQSTR;      // V^T tile: [64 d][64 s]
    bf16* sVl = sVh + 64 * AQSTR;

    const int tid = threadIdx.x;
    const int wid = tid >> 5;
    const int lane = tid & 31;
    const int gid = lane >> 2;
    const int tig = lane & 3;

    const int qt = gridDim.x - 1 - blockIdx.x;   // descending work order
    const int pair = blockIdx.y;
    const int q0 = qt * 64;
    const size_t base = (size_t)pair * S_ * HD_;
    const size_t vtb = (size_t)pair * HD_ * S_;

    // --- stage Q tile (hi/lo) via cp.async ---
    {
        const bf16* srcs[2] = { Qh + base + (size_t)q0 * HD_, Ql + base + (size_t)q0 * HD_ };
#pragma unroll
        for (int a = 0; a < 2; a++)
#pragma unroll
            for (int i = 0; i < 4; i++) {
                int idx = tid + i * 128;
                int r = idx >> 3, u = (idx & 7) << 3;
                cpa16(sb + a * A_ARR_B + (r * AQSTR + u) * 2,
                      srcs[a] + (size_t)r * HD_ + u);
            }
        CPA_COMMIT(); CPA_WAIT(0);
    }
    __syncthreads();

    // Q a-frags in registers, 4 hd k-steps
    uint32_t qh[4][4], ql[4][4];
#pragma unroll
    for (int ks = 0; ks < 4; ks++)
#pragma unroll
        for (int i = 0; i < 4; i++) {
            int r = wid * 16 + gid + 8 * (i & 1);
            int col = ks * 16 + tig * 2 + 8 * (i >> 1);
            qh[ks][i] = *(const uint32_t*)&sQh[r * AQSTR + col];
            ql[ks][i] = *(const uint32_t*)&sQl[r * AQSTR + col];
        }

    float o[8][4];
#pragma unroll
    for (int nt = 0; nt < 8; nt++)
#pragma unroll
        for (int j = 0; j < 4; j++) o[nt][j] = 0.f;
    float m0 = -CUDART_INF_F, m1 = -CUDART_INF_F;
    float l0 = 0.f, l1 = 0.f;

    for (int kt = 0; kt <= qt; kt++) {
        const int k0 = kt * 64;
        __syncthreads();   // prior tile reads done

        // --- K hi/lo + V^T hi/lo tiles via cp.async ---
        {
            const bf16* srcs[4] = { Kh + base + (size_t)k0 * HD_,
                                    Kl + base + (size_t)k0 * HD_,
                                    VTh + vtb + k0,
                                    VTl + vtb + k0 };
            const size_t strd[4] = { HD_, HD_, S_, S_ };
#pragma unroll
            for (int a = 0; a < 4; a++)
#pragma unroll
                for (int i = 0; i < 4; i++) {
                    int idx = tid + i * 128;
                    int r = idx >> 3, u = (idx & 7) << 3;
                    cpa16(sb + (2 + a) * A_ARR_B + (r * AQSTR + u) * 2,
                          srcs[a] + (size_t)r * strd[a] + u);
                }
            CPA_COMMIT(); CPA_WAIT(0);
        }
        __syncthreads();

        // --- scores ---
        float c[8][4];
#pragma unroll
        for (int nt = 0; nt < 8; nt++)
#pragma unroll
            for (int j = 0; j < 4; j++) c[nt][j] = 0.f;

#pragma unroll
        for (int nt = 0; nt < 8; nt++) {
            int n = nt * 8 + gid;
#pragma unroll
            for (int ks = 0; ks < 4; ks++) {
                uint32_t bh[2], bl[2];
                bh[0] = *(const uint32_t*)&sKh[n * AQSTR + ks * 16 + tig * 2];
                bh[1] = *(const uint32_t*)&sKh[n * AQSTR + ks * 16 + 8 + tig * 2];
                bl[0] = *(const uint32_t*)&sKl[n * AQSTR + ks * 16 + tig * 2];
                bl[1] = *(const uint32_t*)&sKl[n * AQSTR + ks * 16 + 8 + tig * 2];
                mma16816(c[nt], qh[ks], bh);
                mma16816(c[nt], qh[ks], bl);
                mma16816(c[nt], ql[ks], bh);
            }
        }

        // --- causal mask (diagonal tile only) ---
        if (kt == qt) {
            int rg = q0 + wid * 16 + gid;
#pragma unroll
            for (int nt = 0; nt < 8; nt++) {
                int cb = k0 + nt * 8 + tig * 2;
                if (cb     > rg)     c[nt][0] = -CUDART_INF_F;
                if (cb + 1 > rg)     c[nt][1] = -CUDART_INF_F;
                if (cb     > rg + 8) c[nt][2] = -CUDART_INF_F;
                if (cb + 1 > rg + 8) c[nt][3] = -CUDART_INF_F;
            }
        }

        // --- online softmax ---
        float mx0 = c[0][0], mx1 = c[0][2];
#pragma unroll
        for (int nt = 0; nt < 8; nt++) {
            mx0 = fmaxf(mx0, fmaxf(c[nt][0], c[nt][1]));
            mx1 = fmaxf(mx1, fmaxf(c[nt][2], c[nt][3]));
        }
        mx0 = fmaxf(mx0, __shfl_xor_sync(0xffffffffu, mx0, 1));
        mx0 = fmaxf(mx0, __shfl_xor_sync(0xffffffffu, mx0, 2));
        mx1 = fmaxf(mx1, __shfl_xor_sync(0xffffffffu, mx1, 1));
        mx1 = fmaxf(mx1, __shfl_xor_sync(0xffffffffu, mx1, 2));

        float mn0 = fmaxf(m0, mx0), mn1 = fmaxf(m1, mx1);
        float f0 = __expf(m0 - mn0), f1 = __expf(m1 - mn1);
        m0 = mn0; m1 = mn1;

        float s0 = 0.f, s1 = 0.f;
#pragma unroll
        for (int nt = 0; nt < 8; nt++) {
            c[nt][0] = __expf(c[nt][0] - mn0);
            c[nt][1] = __expf(c[nt][1] - mn0);
            c[nt][2] = __expf(c[nt][2] - mn1);
            c[nt][3] = __expf(c[nt][3] - mn1);
            s0 += c[nt][0] + c[nt][1];
            s1 += c[nt][2] + c[nt][3];
        }
        s0 += __shfl_xor_sync(0xffffffffu, s0, 1);
        s0 += __shfl_xor_sync(0xffffffffu, s0, 2);
        s1 += __shfl_xor_sync(0xffffffffu, s1, 1);
        s1 += __shfl_xor_sync(0xffffffffu, s1, 2);
        l0 = l0 * f0 + s0;
        l1 = l1 * f1 + s1;
#pragma unroll
        for (int nt = 0; nt < 8; nt++) {
            o[nt][0] *= f0; o[nt][1] *= f0;
            o[nt][2] *= f1; o[nt][3] *= f1;
        }

        // --- P @ V (split P from score fragments; V^T tile in smem) ---
#pragma unroll
        for (int ks = 0; ks < 4; ks++) {
            uint32_t pah[4], pal[4];
            split2(c[2 * ks][0],     c[2 * ks][1],     pah[0], pal[0]);
            split2(c[2 * ks][2],     c[2 * ks][3],     pah[1], pal[1]);
            split2(c[2 * ks + 1][0], c[2 * ks + 1][1], pah[2], pal[2]);
            split2(c[2 * ks + 1][2], c[2 * ks + 1][3], pah[3], pal[3]);
#pragma unroll
            for (int nt = 0; nt < 8; nt++) {
                int n = nt * 8 + gid;
                uint32_t bh[2], bl[2];
                bh[0] = *(const uint32_t*)&sVh[n * AQSTR + ks * 16 + tig * 2];
                bh[1] = *(const uint32_t*)&sVh[n * AQSTR + ks * 16 + 8 + tig * 2];
                bl[0] = *(const uint32_t*)&sVl[n * AQSTR + ks * 16 + tig * 2];
                bl[1] = *(const uint32_t*)&sVl[n * AQSTR + ks * 16 + 8 + tig * 2];
                mma16816(o[nt], pah, bh);
                mma16816(o[nt], pah, bl);
                mma16816(o[nt], pal, bh);
            }
        }
    }

    // --- epilogue: normalize, split to bf16 hi/lo merged-head [M,512] ---
    float inv0 = 1.0f / l0, inv1 = 1.0f / l1;
    const int bb = pair >> 3, h = pair & 7;
    const int rg = q0 + wid * 16 + gid;
    const size_t r0off = ((size_t)bb * S_ + rg) * D_ + h * HD_;
    const size_t r1off = r0off + 8 * D_;
#pragma unroll
    for (int nt = 0; nt < 8; nt++) {
        int d = nt * 8 + tig * 2;
        uint32_t hi, lo;
        split2(o[nt][0] * inv0, o[nt][1] * inv0, hi, lo);
        *(uint32_t*)(Oh + r0off + d) = hi;
        *(uint32_t*)(Ol + r0off + d) = lo;
        split2(o[nt][2] * inv1, o[nt][3] * inv1, hi, lo);
        *(uint32_t*)(Oh + r1off + d) = hi;
        *(uint32_t*)(Ol + r1off + d) = lo;
    }
}

// ===========================================================================
// Launch
// ===========================================================================
extern "C" void kernel_launch(void* const* d_in, const int* in_sizes, int n_in,
                              void* d_out, int out_size)
{
    const float* q_in = (const float*)d_in[0];
    const float* k_in = (const float*)d_in[1];
    const float* v_in = (const float*)d_in[2];
    const float* Wq   = (const float*)d_in[3];
    const float* bq   = (const float*)d_in[4];
    const float* Wk   = (const float*)d_in[5];
    const float* bk   = (const float*)d_in[6];
    const float* Wv   = (const float*)d_in[7];
    const float* bv   = (const float*)d_in[8];
    const float* Wo   = (const float*)d_in[9];
    const float* bo   = (const float*)d_in[10];
    float* out = (float*)d_out;

    bf16 *dAqh, *dAql, *dAkh, *dAkl, *dAvh, *dAvl, *dBh, *dBl;
    bf16 *dQh, *dQl, *dKh, *dKl, *dVh, *dVl, *dVTh, *dVTl;
    cudaGetSymbolAddress((void**)&dAqh, g_Aqh);
    cudaGetSymbolAddress((void**)&dAql, g_Aql);
    cudaGetSymbolAddress((void**)&dAkh, g_Akh);
    cudaGetSymbolAddress((void**)&dAkl, g_Akl);
    cudaGetSymbolAddress((void**)&dAvh, g_Avh);
    cudaGetSymbolAddress((void**)&dAvl, g_Avl);
    cudaGetSymbolAddress((void**)&dBh, g_Bh);
    cudaGetSymbolAddress((void**)&dBl, g_Bl);
    cudaGetSymbolAddress((void**)&dQh, g_Qh);
    cudaGetSymbolAddress((void**)&dQl, g_Ql);
    cudaGetSymbolAddress((void**)&dKh, g_Kh);
    cudaGetSymbolAddress((void**)&dKl, g_Kl);
    cudaGetSymbolAddress((void**)&dVh, g_Vh);
    cudaGetSymbolAddress((void**)&dVl, g_Vl);
    cudaGetSymbolAddress((void**)&dVTh, g_VTh);
    cudaGetSymbolAddress((void**)&dVTl, g_VTl);

    cudaFuncSetAttribute(attn_mma_kernel,
                         cudaFuncAttributeMaxDynamicSharedMemorySize,
                         ATTN_SMEM_BYTES);
    cudaFuncSetAttribute(gemm_mma_kernel,
                         cudaFuncAttributeMaxDynamicSharedMemorySize,
                         GEMM_SMEM_BYTES);

    dim3 ggrid(D_ / 128, M_ / 128);               // (4, 64)
    const int sgrid = (M_ * D_ / 4) / 256;

    // all weight splits + all input splits (2 launches)
    split_w4_kernel<<<dim3(16, 16, 4), dim3(32, 32)>>>(Wq, Wk, Wv, Wo, dBh, dBl);
    split_in3_kernel<<<dim3(sgrid, 3), 256>>>(
        (const float4*)q_in, (const float4*)k_in, (const float4*)v_in,
        (uint32_t*)dAqh, (uint32_t*)dAql,
        (uint32_t*)dAkh, (uint32_t*)dAkl,
        (uint32_t*)dAvh, (uint32_t*)dAvl);

    // projections (Q pre-scaled by 1/sqrt(hd)=0.125)
    gemm_mma_kernel<<<ggrid, 256, GEMM_SMEM_BYTES>>>(
        dAqh, dAql, dBh + 0 * DD_, dBl + 0 * DD_, bq, nullptr, dQh, dQl, 1, 0.125f);
    gemm_mma_kernel<<<ggrid, 256, GEMM_SMEM_BYTES>>>(
        dAkh, dAkl, dBh + 1 * DD_, dBl + 1 * DD_, bk, nullptr, dKh, dKl, 1, 1.0f);
    gemm_mma_kernel<<<ggrid, 256, GEMM_SMEM_BYTES>>>(
        dAvh, dAvl, dBh + 2 * DD_, dBl + 2 * DD_, bv, nullptr, dVh, dVl, 1, 1.0f);

    // V transpose once
    vt_kernel<<<dim3(S_ / 32, HD_ / 32, B_ * H_), 256>>>(dVh, dVl, dVTh, dVTl);

    // causal flash attention -> split merged-head output (reuse Aq buffers)
    dim3 agrid(S_ / 64, B_ * H_);                 // (32, 32)
    attn_mma_kernel<<<agrid, 128, ATTN_SMEM_BYTES>>>(
        dQh, dQl, dKh, dKl, dVTh, dVTl, dAqh, dAql);

    // output projection (fp32 out)
    gemm_mma_kernel<<<ggrid, 256, GEMM_SMEM_BYTES>>>(
        dAqh, dAql, dBh + 3 * DD_, dBl + 3 * DD_, bo, out, nullptr, nullptr, 0, 1.0f);
}